// round 3
// baseline (speedup 1.0000x reference)
#include <cuda_runtime.h>
#include <math.h>

#define HID   512
#define BT    16
#define TT    2048
#define ISZ   32
#define NBLK  128
#define NTH   256
#define UNITS 4

// shared-memory pitches (floats), chosen for 16B alignment + bank spread
#define PW0 552    // 16 rows x 544 used (w_hh0 | w_ih0)
#define PW1 1028   // 16 rows x 1024 used (w_ih1 | w_hh1)
#define PX  1060   // 16 batches x 1056 used (h_a | x_t | h_b)

#define OFF_W1   (16 * PW0)
#define OFF_X    (OFF_W1 + 16 * PW1)
#define OFF_RED  (OFF_X + 16 * PX)
#define OFF_GV   (OFF_RED + 4096)
#define OFF_BIAS (OFF_GV + 512)
#define SMEM_FLOATS (OFF_BIAS + 32)
#define SMEM_MAIN (SMEM_FLOATS * 4)

#define PWO 516
#define SMEM_Y ((32 * PWO + 16 * 512) * 4)

#define YSZ (BT * TT * ISZ)

// ---------------- device scratch (static: no allocations allowed) ----------
__device__ float g_hA[2][BT][HID];            // layer0 h, double buffered
__device__ float g_hB[2][BT][HID];            // layer1 h, double buffered
__device__ float g_h2[(size_t)TT * BT * HID]; // layer1 outputs for y projection (64MB)
__device__ unsigned g_bar_count;
__device__ unsigned g_bar_gen;

__global__ void init_zero_kernel() {
    int i = blockIdx.x * blockDim.x + threadIdx.x;
    if (i < 2 * BT * HID) {
        (&g_hA[0][0][0])[i] = 0.0f;
        (&g_hB[0][0][0])[i] = 0.0f;
    }
    if (i == 0) { g_bar_count = 0u; g_bar_gen = 0u; }
}

__device__ __forceinline__ void grid_barrier() {
    __syncthreads();
    if (threadIdx.x == 0) {
        volatile unsigned* genp = &g_bar_gen;
        unsigned gen = *genp;
        __threadfence();
        unsigned ticket = atomicAdd(&g_bar_count, 1u);
        if (ticket == NBLK - 1) {
            g_bar_count = 0u;   // reset before release
            __threadfence();
            atomicAdd(&g_bar_gen, 1u);
        } else {
            while (*genp == gen) { }
        }
    }
    __syncthreads();
}

__device__ __forceinline__ float sigf(float v) { return 1.0f / (1.0f + __expf(-v)); }

// ---------------------------------------------------------------------------
// Persistent fused 2-layer LSTM. Block b owns hidden units [4b, 4b+4) of BOTH
// layers. Iteration n: layer0 computes step n, layer1 computes step n-1.
// ---------------------------------------------------------------------------
__global__ void __launch_bounds__(NTH, 1) lstm_kernel(
    const float* __restrict__ x,
    const float* __restrict__ w_ih0, const float* __restrict__ w_hh0,
    const float* __restrict__ b_ih0, const float* __restrict__ b_hh0,
    const float* __restrict__ w_ih1, const float* __restrict__ w_hh1,
    const float* __restrict__ b_ih1, const float* __restrict__ b_hh1,
    float* __restrict__ out)
{
    extern __shared__ float sm[];
    const int tid = threadIdx.x;
    const int j0  = blockIdx.x * UNITS;

    // ---- load persistent weight slices into shared (once) ----
    // sW0 row r (= gate g*4 + unit u): cols [0,512)=w_hh0, [512,544)=w_ih0
    for (int i = tid; i < 16 * 544; i += NTH) {
        int r = i / 544, k = i - r * 544;
        int grow = (r >> 2) * HID + j0 + (r & 3);
        float v = (k < 512) ? w_hh0[grow * HID + k] : w_ih0[grow * ISZ + (k - 512)];
        sm[r * PW0 + k] = v;
    }
    // sW1 row r: cols [0,512)=w_ih1 (vs h_a), [512,1024)=w_hh1 (vs h_b)
    for (int i = tid; i < 16 * 1024; i += NTH) {
        int r = i >> 10, k = i & 1023;
        int grow = (r >> 2) * HID + j0 + (r & 3);
        float v = (k < 512) ? w_ih1[grow * HID + k] : w_hh1[grow * HID + (k - 512)];
        sm[OFF_W1 + r * PW1 + k] = v;
    }
    if (tid < 32) {
        int r = tid & 15;
        int grow = (r >> 2) * HID + j0 + (r & 3);
        sm[OFF_BIAS + tid] = (tid < 16) ? (b_ih0[grow] + b_hh0[grow])
                                        : (b_ih1[grow] + b_hh1[grow]);
    }
    __syncthreads();

    // activation-thread persistent state (tid < 128): (layer, unit, batch)
    const int act_layer = tid >> 6;
    const int act_u     = (tid >> 4) & 3;
    const int act_b     = tid & 15;
    float c_reg = 0.0f, h_last = 0.0f;

    for (int n = 0; n <= TT; n++) {
        const int wr = n & 1, rd = wr ^ 1;

        // ---- stage h_a, h_b (prev step) and x[n] into shared ----
        for (int i = tid; i < BT * 128; i += NTH) {
            const int b = i >> 7;
            const int k = (i & 127) << 2;
            float4 va = __ldcg((const float4*)&g_hA[rd][b][k]);
            float4 vb = __ldcg((const float4*)&g_hB[rd][b][k]);
            *(float4*)&sm[OFF_X + b * PX + k]       = va;
            *(float4*)&sm[OFF_X + b * PX + 544 + k] = vb;
        }
        if (n < TT) {
            for (int i = tid; i < BT * 8; i += NTH) {
                const int b = i >> 3;
                const int k = (i & 7) << 2;
                *(float4*)&sm[OFF_X + b * PX + 512 + k] =
                    *(const float4*)&x[((size_t)b * TT + n) * ISZ + k];
            }
        }
        __syncthreads();

        // ---- GEMMs: 32 rows x 16 batches, K-split by 8, 4x4 register tiles
        if (tid < 128) {
            if (n < TT) {  // layer 0 gates: K = 544
                const int ks = tid >> 4, rowgrp = (tid >> 2) & 3, bgrp = tid & 3;
                float acc[4][4];
                #pragma unroll
                for (int a = 0; a < 4; a++)
                    #pragma unroll
                    for (int b2 = 0; b2 < 4; b2++) acc[a][b2] = 0.0f;
                const int kb = ks * 68;
                #pragma unroll 2
                for (int kq = 0; kq < 17; kq++) {
                    const int k = kb + (kq << 2);
                    float4 wv[4], hv[4];
                    #pragma unroll
                    for (int a = 0; a < 4; a++)
                        wv[a] = *(const float4*)&sm[(rowgrp + (a << 2)) * PW0 + k];
                    #pragma unroll
                    for (int b2 = 0; b2 < 4; b2++)
                        hv[b2] = *(const float4*)&sm[OFF_X + (bgrp + (b2 << 2)) * PX + k];
                    #pragma unroll
                    for (int a = 0; a < 4; a++)
                        #pragma unroll
                        for (int b2 = 0; b2 < 4; b2++)
                            acc[a][b2] += wv[a].x * hv[b2].x + wv[a].y * hv[b2].y
                                        + wv[a].z * hv[b2].z + wv[a].w * hv[b2].w;
                }
                #pragma unroll
                for (int a = 0; a < 4; a++)
                    #pragma unroll
                    for (int b2 = 0; b2 < 4; b2++) {
                        int row = rowgrp + (a << 2), bb = bgrp + (b2 << 2);
                        sm[OFF_RED + (((row << 4) + bb) << 3) + ks] = acc[a][b2];
                    }
            }
        } else {
            if (n >= 1) {  // layer 1 gates: K = 1024 (h_a | h_b)
                const int t2 = tid - 128;
                const int ks = t2 >> 4, rowgrp = (t2 >> 2) & 3, bgrp = t2 & 3;
                float acc[4][4];
                #pragma unroll
                for (int a = 0; a < 4; a++)
                    #pragma unroll
                    for (int b2 = 0; b2 < 4; b2++) acc[a][b2] = 0.0f;
                const int kb = ks << 7;
                const int sxofs = (ks >= 4) ? 32 : 0;  // skip x-slot in sX
                #pragma unroll 2
                for (int kq = 0; kq < 32; kq++) {
                    const int k = kb + (kq << 2);
                    float4 wv[4], hv[4];
                    #pragma unroll
                    for (int a = 0; a < 4; a++)
                        wv[a] = *(const float4*)&sm[OFF_W1 + (rowgrp + (a << 2)) * PW1 + k];
                    #pragma unroll
                    for (int b2 = 0; b2 < 4; b2++)
                        hv[b2] = *(const float4*)&sm[OFF_X + (bgrp + (b2 << 2)) * PX + k + sxofs];
                    #pragma unroll
                    for (int a = 0; a < 4; a++)
                        #pragma unroll
                        for (int b2 = 0; b2 < 4; b2++)
                            acc[a][b2] += wv[a].x * hv[b2].x + wv[a].y * hv[b2].y
                                        + wv[a].z * hv[b2].z + wv[a].w * hv[b2].w;
                }
                #pragma unroll
                for (int a = 0; a < 4; a++)
                    #pragma unroll
                    for (int b2 = 0; b2 < 4; b2++) {
                        int row = 16 + rowgrp + (a << 2), bb = bgrp + (b2 << 2);
                        sm[OFF_RED + (((row << 4) + bb) << 3) + ks] = acc[a][b2];
                    }
            }
        }
        __syncthreads();

        // ---- K-split reduction + bias ----
        for (int o = tid; o < 512; o += NTH) {
            const float* rp = &sm[OFF_RED + (o << 3)];
            float s = 0.0f;
            #pragma unroll
            for (int p = 0; p < 8; p++) s += rp[p];
            sm[OFF_GV + o] = s + sm[OFF_BIAS + (o >> 4)];
        }
        __syncthreads();

        // ---- gate activations + state update ----
        if (tid < 128) {
            const bool active = (act_layer == 0) ? (n < TT) : (n >= 1);
            if (active) {
                const int base = act_layer * 256;
                float gi = sm[OFF_GV + base + ((0 * 4 + act_u) << 4) + act_b];
                float gf = sm[OFF_GV + base + ((1 * 4 + act_u) << 4) + act_b];
                float gg = sm[OFF_GV + base + ((2 * 4 + act_u) << 4) + act_b];
                float go = sm[OFF_GV + base + ((3 * 4 + act_u) << 4) + act_b];
                float iv = sigf(gi), fv = sigf(gf), ov = sigf(go);
                float gv = tanhf(gg);
                c_reg = fv * c_reg + iv * gv;
                h_last = ov * tanhf(c_reg);
                const int j = j0 + act_u;
                if (act_layer == 0) {
                    g_hA[wr][act_b][j] = h_last;
                } else {
                    g_hB[wr][act_b][j] = h_last;
                    g_h2[((size_t)(n - 1) * BT + act_b) * HID + j] = h_last;
                }
            }
        }
        __threadfence();
        grid_barrier();
    }

    // ---- final h_n, c_n from register state ----
    if (tid < 128) {
        const int j = j0 + act_u;
        out[YSZ + (act_layer * BT + act_b) * HID + j] = h_last;
        out[YSZ + 2 * BT * HID + (act_layer * BT + act_b) * HID + j] = c_reg;
    }
}

// ---------------------------------------------------------------------------
// y[b,t,:] = h2[t,b,:] @ w_out^T + b_out   (one block per t, 16 batches each)
// ---------------------------------------------------------------------------
__global__ void __launch_bounds__(NTH) y_proj_kernel(
    const float* __restrict__ w_out, const float* __restrict__ b_out,
    float* __restrict__ out)
{
    extern __shared__ float sm[];
    float* sWo = sm;               // 32 x PWO
    float* sH  = sm + 32 * PWO;    // 16 x 512
    const int t = blockIdx.x;
    const int tid = threadIdx.x;

    for (int i = tid; i < 32 * 128; i += NTH) {
        int o = i >> 7, k = (i & 127) << 2;
        *(float4*)&sWo[o * PWO + k] = *(const float4*)&w_out[o * HID + k];
    }
    for (int i = tid; i < 16 * 128; i += NTH) {
        int b = i >> 7, k = (i & 127) << 2;
        *(float4*)&sH[b * HID + k] =
            *(const float4*)&g_h2[((size_t)t * BT + b) * HID + k];
    }
    __syncthreads();

    const int b = tid >> 4, oc = tid & 15;
    float a0 = 0.0f, a1 = 0.0f;
    #pragma unroll 4
    for (int k = 0; k < HID; k += 4) {
        float4 hk = *(const float4*)&sH[b * HID + k];
        float4 w0 = *(const float4*)&sWo[oc * PWO + k];
        float4 w1 = *(const float4*)&sWo[(oc + 16) * PWO + k];
        a0 += hk.x * w0.x + hk.y * w0.y + hk.z * w0.z + hk.w * w0.w;
        a1 += hk.x * w1.x + hk.y * w1.y + hk.z * w1.z + hk.w * w1.w;
    }
    out[((size_t)b * TT + t) * ISZ + oc]      = a0 + b_out[oc];
    out[((size_t)b * TT + t) * ISZ + oc + 16] = a1 + b_out[oc + 16];
}

// ---------------------------------------------------------------------------
extern "C" void kernel_launch(void* const* d_in, const int* in_sizes, int n_in,
                              void* d_out, int out_size)
{
    const float* x     = (const float*)d_in[0];
    const float* w_ih0 = (const float*)d_in[1];
    const float* w_hh0 = (const float*)d_in[2];
    const float* b_ih0 = (const float*)d_in[3];
    const float* b_hh0 = (const float*)d_in[4];
    const float* w_ih1 = (const float*)d_in[5];
    const float* w_hh1 = (const float*)d_in[6];
    const float* b_ih1 = (const float*)d_in[7];
    const float* b_hh1 = (const float*)d_in[8];
    const float* w_out = (const float*)d_in[9];
    const float* b_out = (const float*)d_in[10];
    float* out = (float*)d_out;

    cudaFuncSetAttribute(lstm_kernel, cudaFuncAttributeMaxDynamicSharedMemorySize, SMEM_MAIN);
    cudaFuncSetAttribute(y_proj_kernel, cudaFuncAttributeMaxDynamicSharedMemorySize, SMEM_Y);

    init_zero_kernel<<<64, NTH>>>();
    lstm_kernel<<<NBLK, NTH, SMEM_MAIN>>>(x, w_ih0, w_hh0, b_ih0, b_hh0,
                                          w_ih1, w_hh1, b_ih1, b_hh1, out);
    y_proj_kernel<<<TT, NTH, SMEM_Y>>>(w_out, b_out, out);
}

// round 4
// speedup vs baseline: 1.6352x; 1.6352x over previous
#include <cuda_runtime.h>
#include <cuda_bf16.h>

#define HID 512
#define BT  16
#define TT  2048
#define ISZ 32
#define NBLK 128
#define NTH  256
#define YSZ (BT*TT*ISZ)

// smem word (b32 = 2 bf16) pitches; all ≡ 4 (mod 32) for conflict-free frags
#define PW0W 292   // layer0 A: 288 words used (K=576: 512 h + 32 x + 32 pad)
#define PW1W 516   // layer1 A: 512 words used (K=1024)
#define PHW  548   // B (h/x): 544 words used

#define OW0HI 0
#define OW0LO (OW0HI + 16*PW0W)
#define OW1HI (OW0LO + 16*PW0W)
#define OW1LO (OW1HI + 16*PW1W)
#define OHHI  (OW1LO + 16*PW1W)
#define OHLO  (OHHI + 16*PHW)
#define ORED  (OHLO + 16*PHW)     // 4 partials x 512 floats
#define OBIAS (ORED + 2048)
#define SMEM_WORDS (OBIAS + 32)
#define SMEM_MAIN (SMEM_WORDS*4)

#define PWO 516
#define SMEM_Y ((32*PWO + 16*512)*4)

// ----------------- device scratch ------------------------------------------
__device__ __align__(16) unsigned g_hHI[2][2][BT][256]; // [buf][layer][b][kword]
__device__ __align__(16) unsigned g_hLO[2][2][BT][256];
__device__ __align__(16) unsigned g_xHI[TT][BT][16];
__device__ __align__(16) unsigned g_xLO[TT][BT][16];
__device__ float g_h2[(size_t)TT*BT*HID];
__device__ unsigned g_bar_count, g_bar_gen;

// ----------------- helpers --------------------------------------------------
__device__ __forceinline__ void split2(float f0, float f1, unsigned &hi, unsigned &lo) {
    unsigned h;
    asm("cvt.rn.bf16x2.f32 %0, %1, %2;" : "=r"(h) : "f"(f1), "f"(f0));
    float r0 = f0 - __uint_as_float(h << 16);
    float r1 = f1 - __uint_as_float(h & 0xFFFF0000u);
    unsigned l;
    asm("cvt.rn.bf16x2.f32 %0, %1, %2;" : "=r"(l) : "f"(r1), "f"(r0));
    hi = h; lo = l;
}

__device__ __forceinline__ void mma_bf16(float* c, const unsigned* a, const unsigned* b) {
    asm volatile(
        "mma.sync.aligned.m16n8k16.row.col.f32.bf16.bf16.f32 "
        "{%0,%1,%2,%3}, {%4,%5,%6,%7}, {%8,%9}, {%0,%1,%2,%3};"
        : "+f"(c[0]), "+f"(c[1]), "+f"(c[2]), "+f"(c[3])
        : "r"(a[0]), "r"(a[1]), "r"(a[2]), "r"(a[3]), "r"(b[0]), "r"(b[1]));
}

__device__ __forceinline__ float sigf(float v) {
    return __fdividef(1.0f, 1.0f + __expf(-v));
}
__device__ __forceinline__ float tanh_fast(float v) {
    return __fdividef(2.0f, 1.0f + __expf(-2.0f * v)) - 1.0f;
}

__device__ __forceinline__ void grid_barrier() {
    __syncthreads();
    if (threadIdx.x == 0) {
        volatile unsigned* genp = &g_bar_gen;
        unsigned gen = *genp;
        __threadfence();
        unsigned ticket = atomicAdd(&g_bar_count, 1u);
        if (ticket == NBLK - 1) {
            g_bar_count = 0u;
            __threadfence();
            atomicAdd(&g_bar_gen, 1u);
        } else {
            while (*genp == gen) { }
        }
    }
    __syncthreads();
}

// ----------------- init kernels ---------------------------------------------
__global__ void init_zero_kernel() {
    int i = blockIdx.x * blockDim.x + threadIdx.x;
    if (i < 2*2*BT*256) {
        (&g_hHI[0][0][0][0])[i] = 0u;
        (&g_hLO[0][0][0][0])[i] = 0u;
    }
    if (i == 0) { g_bar_count = 0u; g_bar_gen = 0u; }
}

__global__ void x_split_kernel(const float* __restrict__ x) {
    int idx = blockIdx.x * blockDim.x + threadIdx.x;   // over TT*BT*16 words
    if (idx >= TT*BT*16) return;
    int t = idx >> 8;
    int r = idx & 255;
    int b = r >> 4, w = r & 15;
    const float* xp = &x[((size_t)b*TT + t)*ISZ + 2*w];
    unsigned hi, lo;
    split2(xp[0], xp[1], hi, lo);
    g_xHI[t][b][w] = hi;
    g_xLO[t][b][w] = lo;
}

// ----------------- persistent fused 2-layer LSTM ----------------------------
__global__ void __launch_bounds__(NTH, 1) lstm_kernel(
    const float* __restrict__ w_ih0, const float* __restrict__ w_hh0,
    const float* __restrict__ b_ih0, const float* __restrict__ b_hh0,
    const float* __restrict__ w_ih1, const float* __restrict__ w_hh1,
    const float* __restrict__ b_ih1, const float* __restrict__ b_hh1,
    float* __restrict__ out)
{
    extern __shared__ unsigned smu[];
    float* red  = reinterpret_cast<float*>(&smu[ORED]);
    float* bias = reinterpret_cast<float*>(&smu[OBIAS]);
    const int tid = threadIdx.x;
    const int j0  = blockIdx.x * 4;

    // ---- one-time: split weights into bf16 hi/lo words in shared ----
    // W0 rows r=g*4+u, word w: k=2w,2w+1 of [w_hh0 | w_ih0 | zero-pad]
    for (int i = tid; i < 16*288; i += NTH) {
        int r = i / 288, w = i - r*288;
        int grow = (r >> 2)*HID + j0 + (r & 3);
        int k0 = 2*w;
        float f0, f1;
        f0 = (k0 < 512) ? w_hh0[grow*HID + k0]
           : (k0 < 544) ? w_ih0[grow*ISZ + (k0-512)] : 0.0f;
        int k1 = k0 + 1;
        f1 = (k1 < 512) ? w_hh0[grow*HID + k1]
           : (k1 < 544) ? w_ih0[grow*ISZ + (k1-512)] : 0.0f;
        unsigned hi, lo; split2(f0, f1, hi, lo);
        smu[OW0HI + r*PW0W + w] = hi;
        smu[OW0LO + r*PW0W + w] = lo;
    }
    // W1 rows: word w: cols [w_ih1 (vs h_a) | w_hh1 (vs h_b)]
    for (int i = tid; i < 16*512; i += NTH) {
        int r = i >> 9, w = i & 511;
        int grow = (r >> 2)*HID + j0 + (r & 3);
        int c0 = 2*w;
        float f0 = (c0 < 512) ? w_ih1[grow*HID + c0] : w_hh1[grow*HID + (c0-512)];
        int c1 = c0 + 1;
        float f1 = (c1 < 512) ? w_ih1[grow*HID + c1] : w_hh1[grow*HID + (c1-512)];
        unsigned hi, lo; split2(f0, f1, hi, lo);
        smu[OW1HI + r*PW1W + w] = hi;
        smu[OW1LO + r*PW1W + w] = lo;
    }
    if (tid < 32) {
        int l = tid >> 4, r = tid & 15;
        int grow = (r >> 2)*HID + j0 + (r & 3);
        bias[tid] = l ? (b_ih1[grow] + b_hh1[grow]) : (b_ih0[grow] + b_hh0[grow]);
    }
    // zero the x pad region (words 272..287) of B staging, hi and lo
    for (int i = tid; i < 16*16; i += NTH) {
        int b = i >> 4, w = i & 15;
        smu[OHHI + b*PHW + 272 + w] = 0u;
        smu[OHLO + b*PHW + 272 + w] = 0u;
    }
    __syncthreads();

    // warp roles for GEMM
    const int wid   = tid >> 5;
    const int lane  = tid & 31;
    const int layer = wid >> 2;       // 0..1
    const int ks    = wid & 3;        // K-split 0..3
    // act-thread roles (tid < 128)
    const int layerA = tid >> 6;
    const int uA     = (tid >> 4) & 3;
    const int bA     = tid & 15;
    float c_reg = 0.0f, h_last = 0.0f;

    for (int n = 0; n <= TT; n++) {
        const int wr = n & 1, rd = wr ^ 1;

        // ---- stage h (both layers, hi+lo) into shared --------------------
        {
            const uint4* srcH = (const uint4*)&g_hHI[rd][0][0][0];
            const uint4* srcL = (const uint4*)&g_hLO[rd][0][0][0];
            #pragma unroll
            for (int it = 0; it < 8; it++) {
                int i = tid + it*NTH;              // 0..2047
                int lyr = i >> 10;
                int b   = (i >> 6) & 15;
                int w4  = i & 63;
                int dst = b*PHW + lyr*288 + w4*4;
                *(uint4*)&smu[OHHI + dst] = __ldcg(&srcH[i]);
                *(uint4*)&smu[OHLO + dst] = __ldcg(&srcL[i]);
            }
            if (n < TT && tid < 64) {
                int b = tid >> 2, w4 = tid & 3;
                int dst = b*PHW + 256 + w4*4;
                *(uint4*)&smu[OHHI + dst] = __ldg((const uint4*)&g_xHI[n][0][0] + tid);
                *(uint4*)&smu[OHLO + dst] = __ldg((const uint4*)&g_xLO[n][0][0] + tid);
            }
        }
        __syncthreads();

        // ---- tensor-core GEMMs (split-bf16, fp32 accum) -------------------
        {
            const bool run = (layer == 0) ? (n < TT) : (n >= 1);
            if (run) {
                float acc0[4] = {0,0,0,0}, acc1[4] = {0,0,0,0};
                const int ntl    = (layer == 0) ? 9 : 16;
                const int ktbase = (layer == 0) ? ks*9 : ks*16;
                const unsigned* Ahi = &smu[layer ? OW1HI : OW0HI];
                const int APW = layer ? PW1W : PW0W;
                const unsigned* Alo = Ahi + 16*APW;
                const unsigned* Bhi = &smu[OHHI];
                const unsigned* Blo = &smu[OHLO];
                const int arow = lane >> 2;
                const int tig  = lane & 3;
                const int bcol = lane >> 2;

                for (int kt = ktbase; kt < ktbase + ntl; kt++) {
                    const int awb = kt*8;
                    const int wb  = (layer == 0) ? kt*8
                                  : ((kt < 32) ? kt*8 : 288 + (kt-32)*8);
                    unsigned ah[4], al[4];
                    ah[0] = Ahi[ arow     *APW + awb     + tig];
                    ah[1] = Ahi[(arow+8)  *APW + awb     + tig];
                    ah[2] = Ahi[ arow     *APW + awb + 4 + tig];
                    ah[3] = Ahi[(arow+8)  *APW + awb + 4 + tig];
                    al[0] = Alo[ arow     *APW + awb     + tig];
                    al[1] = Alo[(arow+8)  *APW + awb     + tig];
                    al[2] = Alo[ arow     *APW + awb + 4 + tig];
                    al[3] = Alo[(arow+8)  *APW + awb + 4 + tig];

                    unsigned bh0[2], bl0[2], bh1[2], bl1[2];
                    bh0[0] = Bhi[ bcol    *PHW + wb     + tig];
                    bh0[1] = Bhi[ bcol    *PHW + wb + 4 + tig];
                    bh1[0] = Bhi[(bcol+8) *PHW + wb     + tig];
                    bh1[1] = Bhi[(bcol+8) *PHW + wb + 4 + tig];
                    bl0[0] = Blo[ bcol    *PHW + wb     + tig];
                    bl0[1] = Blo[ bcol    *PHW + wb + 4 + tig];
                    bl1[0] = Blo[(bcol+8) *PHW + wb     + tig];
                    bl1[1] = Blo[(bcol+8) *PHW + wb + 4 + tig];

                    mma_bf16(acc0, ah, bh0);
                    mma_bf16(acc0, ah, bl0);
                    mma_bf16(acc0, al, bh0);
                    mma_bf16(acc1, ah, bh1);
                    mma_bf16(acc1, ah, bl1);
                    mma_bf16(acc1, al, bh1);
                }
                // store partials: red[ks*512 + layer*256 + row*16 + batch]
                const int base = ks*512 + layer*256;
                const int row  = lane >> 2;
                const int col  = (lane & 3)*2;
                *(float2*)&red[base +  row    *16 + col    ] = make_float2(acc0[0], acc0[1]);
                *(float2*)&red[base + (row+8) *16 + col    ] = make_float2(acc0[2], acc0[3]);
                *(float2*)&red[base +  row    *16 + col + 8] = make_float2(acc1[0], acc1[1]);
                *(float2*)&red[base + (row+8) *16 + col + 8] = make_float2(acc1[2], acc1[3]);
            }
        }
        __syncthreads();

        // ---- reduce partials + activations + state update ----------------
        if (tid < 128) {
            const bool active = (layerA == 0) ? (n < TT) : (n >= 1);
            if (active) {
                float gs[4];
                #pragma unroll
                for (int g = 0; g < 4; g++) {
                    int idx = layerA*256 + (g*4 + uA)*16 + bA;
                    gs[g] = red[idx] + red[512 + idx] + red[1024 + idx] + red[1536 + idx]
                          + bias[layerA*16 + g*4 + uA];
                }
                float iv = sigf(gs[0]), fv = sigf(gs[1]);
                float gv = tanh_fast(gs[2]), ov = sigf(gs[3]);
                c_reg = fv * c_reg + iv * gv;
                h_last = ov * tanh_fast(c_reg);

                // pack (even unit, odd unit) pairs and publish split-bf16 h
                float hp = __shfl_xor_sync(0xffffffffu, h_last, 16);
                if ((tid & 16) == 0) {
                    unsigned whi, wlo; split2(h_last, hp, whi, wlo);
                    int widx = blockIdx.x*2 + (uA >> 1);
                    g_hHI[wr][layerA][bA][widx] = whi;
                    g_hLO[wr][layerA][bA][widx] = wlo;
                }
                if (layerA == 1) {
                    g_h2[((size_t)(n-1)*BT + bA)*HID + j0 + uA] = h_last;
                }
            }
        }
        __threadfence();
        grid_barrier();
    }

    // ---- final h_n, c_n ----
    if (tid < 128) {
        const int j = j0 + uA;
        out[YSZ + (layerA*BT + bA)*HID + j] = h_last;
        out[YSZ + 2*BT*HID + (layerA*BT + bA)*HID + j] = c_reg;
    }
}

// ----------------- y projection ---------------------------------------------
__global__ void __launch_bounds__(NTH) y_proj_kernel(
    const float* __restrict__ w_out, const float* __restrict__ b_out,
    float* __restrict__ out)
{
    extern __shared__ float sm[];
    float* sWo = sm;
    float* sH  = sm + 32*PWO;
    const int t = blockIdx.x;
    const int tid = threadIdx.x;

    for (int i = tid; i < 32*128; i += NTH) {
        int o = i >> 7, k = (i & 127) << 2;
        *(float4*)&sWo[o*PWO + k] = *(const float4*)&w_out[o*HID + k];
    }
    for (int i = tid; i < 16*128; i += NTH) {
        int b = i >> 7, k = (i & 127) << 2;
        *(float4*)&sH[b*HID + k] = *(const float4*)&g_h2[((size_t)t*BT + b)*HID + k];
    }
    __syncthreads();

    const int b = tid >> 4, oc = tid & 15;
    float a0 = 0.0f, a1 = 0.0f;
    #pragma unroll 4
    for (int k = 0; k < HID; k += 4) {
        float4 hk = *(const float4*)&sH[b*HID + k];
        float4 w0 = *(const float4*)&sWo[oc*PWO + k];
        float4 w1 = *(const float4*)&sWo[(oc+16)*PWO + k];
        a0 += hk.x*w0.x + hk.y*w0.y + hk.z*w0.z + hk.w*w0.w;
        a1 += hk.x*w1.x + hk.y*w1.y + hk.z*w1.z + hk.w*w1.w;
    }
    out[((size_t)b*TT + t)*ISZ + oc]      = a0 + b_out[oc];
    out[((size_t)b*TT + t)*ISZ + oc + 16] = a1 + b_out[oc + 16];
}

// ----------------------------------------------------------------------------
extern "C" void kernel_launch(void* const* d_in, const int* in_sizes, int n_in,
                              void* d_out, int out_size)
{
    const float* x     = (const float*)d_in[0];
    const float* w_ih0 = (const float*)d_in[1];
    const float* w_hh0 = (const float*)d_in[2];
    const float* b_ih0 = (const float*)d_in[3];
    const float* b_hh0 = (const float*)d_in[4];
    const float* w_ih1 = (const float*)d_in[5];
    const float* w_hh1 = (const float*)d_in[6];
    const float* b_ih1 = (const float*)d_in[7];
    const float* b_hh1 = (const float*)d_in[8];
    const float* w_out = (const float*)d_in[9];
    const float* b_out = (const float*)d_in[10];
    float* out = (float*)d_out;

    cudaFuncSetAttribute(lstm_kernel, cudaFuncAttributeMaxDynamicSharedMemorySize, SMEM_MAIN);
    cudaFuncSetAttribute(y_proj_kernel, cudaFuncAttributeMaxDynamicSharedMemorySize, SMEM_Y);

    init_zero_kernel<<<64, NTH>>>();
    x_split_kernel<<<(TT*BT*16 + NTH - 1)/NTH, NTH>>>(x);
    lstm_kernel<<<NBLK, NTH, SMEM_MAIN>>>(w_ih0, w_hh0, b_ih0, b_hh0,
                                          w_ih1, w_hh1, b_ih1, b_hh1, out);
    y_proj_kernel<<<TT, NTH, SMEM_Y>>>(w_out, b_out, out);
}

// round 5
// speedup vs baseline: 1.6643x; 1.0178x over previous
#include <cuda_runtime.h>
#include <cuda_bf16.h>

#define HID 512
#define BT  16
#define TT  2048
#define ISZ 32
#define NBLK 128
#define NTH  512
#define YSZ (BT*TT*ISZ)

// word (b32 = 2 bf16) pitches; all ≡ 4 (mod 32)
#define PW0W 324   // layer0 A: words 0..319 used (K padded 576->640, extra pad is zero)
#define PW1W 516   // layer1 A: 512 words (K=1024)
#define PHW  548   // B rows: [0,256) h_a | [256,272) x | [272,288) zero | [288,544) h_b

#define OW0HI 0
#define OW0LO (OW0HI + 16*PW0W)
#define OW1HI (OW0LO + 16*PW0W)
#define OW1LO (OW1HI + 16*PW1W)
#define OHHI  (OW1LO + 16*PW1W)
#define OHLO  (OHHI + 16*PHW)
#define ORED  (OHLO + 16*PHW)     // 16 partials x 256 floats
#define OGV   (ORED + 4096)
#define OBIAS (OGV + 512)
#define SMEM_WORDS (OBIAS + 32)
#define SMEM_MAIN (SMEM_WORDS*4)

#define PWO 516
#define SMEM_Y ((32*PWO + 16*512)*4)

// ----------------- device scratch ------------------------------------------
__device__ __align__(16) unsigned g_hHI[2][2][BT][256]; // [buf][layer][b][kword]
__device__ __align__(16) unsigned g_hLO[2][2][BT][256];
__device__ __align__(16) unsigned g_xHI[TT][BT][16];
__device__ __align__(16) unsigned g_xLO[TT][BT][16];
__device__ float g_h2[(size_t)TT*BT*HID];
__device__ unsigned g_arrive[NBLK];
__device__ unsigned g_release;

// ----------------- helpers --------------------------------------------------
__device__ __forceinline__ void split2(float f0, float f1, unsigned &hi, unsigned &lo) {
    unsigned h;
    asm("cvt.rn.bf16x2.f32 %0, %1, %2;" : "=r"(h) : "f"(f1), "f"(f0));
    float r0 = f0 - __uint_as_float(h << 16);
    float r1 = f1 - __uint_as_float(h & 0xFFFF0000u);
    unsigned l;
    asm("cvt.rn.bf16x2.f32 %0, %1, %2;" : "=r"(l) : "f"(r1), "f"(r0));
    hi = h; lo = l;
}

__device__ __forceinline__ void mma_bf16(float* c, const unsigned* a, const unsigned* b) {
    asm volatile(
        "mma.sync.aligned.m16n8k16.row.col.f32.bf16.bf16.f32 "
        "{%0,%1,%2,%3}, {%4,%5,%6,%7}, {%8,%9}, {%0,%1,%2,%3};"
        : "+f"(c[0]), "+f"(c[1]), "+f"(c[2]), "+f"(c[3])
        : "r"(a[0]), "r"(a[1]), "r"(a[2]), "r"(a[3]), "r"(b[0]), "r"(b[1]));
}

__device__ __forceinline__ void ldsm4(unsigned &r0, unsigned &r1, unsigned &r2, unsigned &r3,
                                      unsigned addr) {
    asm volatile("ldmatrix.sync.aligned.m8n8.x4.shared.b16 {%0,%1,%2,%3}, [%4];"
                 : "=r"(r0), "=r"(r1), "=r"(r2), "=r"(r3) : "r"(addr));
}

__device__ __forceinline__ float sigf(float v) {
    return __fdividef(1.0f, 1.0f + __expf(-v));
}
__device__ __forceinline__ float tanh_fast(float v) {
    return __fdividef(2.0f, 1.0f + __expf(-2.0f * v)) - 1.0f;
}

// distributed-flag grid barrier (no contended atomics)
__device__ __forceinline__ void grid_barrier(int n, int tid) {
    const unsigned tgt = (unsigned)(n + 1);
    __syncthreads();
    if (tid == 0) {
        __threadfence();
        *(volatile unsigned*)&g_arrive[blockIdx.x] = tgt;
    }
    if (blockIdx.x == 0 && tid < 32) {
        volatile unsigned* f = g_arrive + tid * 4;
        for (;;) {
            bool ok = (f[0] >= tgt) & (f[1] >= tgt) & (f[2] >= tgt) & (f[3] >= tgt);
            if (__all_sync(0xffffffffu, ok)) break;
        }
        if (tid == 0) *(volatile unsigned*)&g_release = tgt;
    }
    if (tid == 0) {
        while (*(volatile unsigned*)&g_release < tgt) {}
        __threadfence();
    }
    __syncthreads();
}

// ----------------- init kernels ---------------------------------------------
__global__ void init_zero_kernel() {
    int i = blockIdx.x * blockDim.x + threadIdx.x;
    if (i < 2*2*BT*256) {
        (&g_hHI[0][0][0][0])[i] = 0u;
        (&g_hLO[0][0][0][0])[i] = 0u;
    }
    if (i < NBLK) g_arrive[i] = 0u;
    if (i == 0) g_release = 0u;
}

__global__ void x_split_kernel(const float* __restrict__ x) {
    int idx = blockIdx.x * blockDim.x + threadIdx.x;
    if (idx >= TT*BT*16) return;
    int t = idx >> 8;
    int r = idx & 255;
    int b = r >> 4, w = r & 15;
    const float* xp = &x[((size_t)b*TT + t)*ISZ + 2*w];
    unsigned hi, lo;
    split2(xp[0], xp[1], hi, lo);
    g_xHI[t][b][w] = hi;
    g_xLO[t][b][w] = lo;
}

// ----------------- persistent loop (per-layer specialized) ------------------
// LAYER=0: warps 0-7, NTL=5 tiles each (K padded to 40 tiles; pad A is zero).
// LAYER=1: warps 8-15, NTL=8 tiles each (64 tiles).
// Act threads (tid<128) live in the LAYER=0 copy and own BOTH layers' states.
template<int LAYER, int NTL>
__device__ __forceinline__ void run_loop(
    unsigned* __restrict__ smu, float* __restrict__ red, float* __restrict__ gv,
    float* __restrict__ bias, int tid, int wid, int lane, int start, int j0,
    float* __restrict__ out)
{
    // ---- hoist A fragments (weights) into registers, once ----
    unsigned ah[NTL][4], al[NTL][4];
    {
        const int APW = LAYER ? PW1W : PW0W;
        const unsigned* Ahi = &smu[LAYER ? OW1HI : OW0HI];
        const unsigned* Alo = &smu[LAYER ? OW1LO : OW0LO];
        const int arow = lane >> 2, tig = lane & 3;
        #pragma unroll
        for (int i = 0; i < NTL; i++) {
            const int awb = (start + i) * 8;
            ah[i][0] = Ahi[ arow      * APW + awb     + tig];
            ah[i][1] = Ahi[(arow + 8) * APW + awb     + tig];
            ah[i][2] = Ahi[ arow      * APW + awb + 4 + tig];
            ah[i][3] = Ahi[(arow + 8) * APW + awb + 4 + tig];
            al[i][0] = Alo[ arow      * APW + awb     + tig];
            al[i][1] = Alo[(arow + 8) * APW + awb     + tig];
            al[i][2] = Alo[ arow      * APW + awb + 4 + tig];
            al[i][3] = Alo[(arow + 8) * APW + awb + 4 + tig];
        }
    }
    // ---- B ldmatrix lane addresses ----
    unsigned sbase = (unsigned)__cvta_generic_to_shared(smu);
    const int mm = lane >> 3, rr = lane & 7;
    const int bb = ((mm >> 1) << 3) + rr;
    const unsigned woff = (mm & 1) * 4;
    const unsigned bhi_base = sbase + (OHHI + bb * PHW + woff) * 4u;
    const unsigned blo_base = sbase + (OHLO + bb * PHW + woff) * 4u;
    const int wbase = (LAYER == 0) ? start * 8
                    : ((start < 32) ? start * 8 : 288 + (start - 32) * 8);

    // ---- act roles (only used in LAYER==0 copy) ----
    const int layerA = tid >> 6, uA = (tid >> 4) & 3, bA = tid & 15;
    float c_reg = 0.0f, h_last = 0.0f;

    for (int n = 0; n <= TT; n++) {
        const int wr = n & 1, rd = wr ^ 1;

        // ---- stage h (both layers, hi+lo) + x into shared ----
        {
            const uint4* srcH = (const uint4*)&g_hHI[rd][0][0][0];
            const uint4* srcL = (const uint4*)&g_hLO[rd][0][0][0];
            #pragma unroll
            for (int it = 0; it < 4; it++) {
                int i = tid + it * NTH;           // 0..2047
                int lyr = i >> 10;
                int b   = (i >> 6) & 15;
                int w4  = i & 63;
                int dst = b * PHW + lyr * 288 + (w4 << 2);
                *(uint4*)&smu[OHHI + dst] = __ldcg(&srcH[i]);
                *(uint4*)&smu[OHLO + dst] = __ldcg(&srcL[i]);
            }
            if (n < TT && tid < 128) {
                int half = tid >> 6, t2 = tid & 63;
                int b = t2 >> 2, w4 = t2 & 3;
                int dst = b * PHW + 256 + (w4 << 2);
                const uint4* src = half ? ((const uint4*)&g_xLO[n][0][0])
                                        : ((const uint4*)&g_xHI[n][0][0]);
                *(uint4*)&smu[(half ? OHLO : OHHI) + dst] = __ldg(&src[t2]);
            }
        }
        __syncthreads();

        // ---- tensor-core GEMM (split-bf16, A in registers, B via ldmatrix) ----
        {
            const bool run = (LAYER == 0) ? (n < TT) : (n >= 1);
            if (run) {
                float acc0[4] = {0,0,0,0}, acc1[4] = {0,0,0,0};
                #pragma unroll
                for (int i = 0; i < NTL; i++) {
                    const unsigned wb4 = (unsigned)(wbase + i * 8) * 4u;
                    unsigned b0,b1,b2,b3, l0,l1,l2,l3;
                    ldsm4(b0, b1, b2, b3, bhi_base + wb4);
                    ldsm4(l0, l1, l2, l3, blo_base + wb4);
                    unsigned bh0[2] = {b0, b1}, bh1[2] = {b2, b3};
                    unsigned bl0[2] = {l0, l1}, bl1[2] = {l2, l3};
                    mma_bf16(acc0, ah[i], bh0);
                    mma_bf16(acc0, ah[i], bl0);
                    mma_bf16(acc0, al[i], bh0);
                    mma_bf16(acc1, ah[i], bh1);
                    mma_bf16(acc1, ah[i], bl1);
                    mma_bf16(acc1, al[i], bh1);
                }
                const int base = wid * 256;
                const int row  = lane >> 2;
                const int col  = (lane & 3) * 2;
                *(float2*)&red[base +  row      * 16 + col    ] = make_float2(acc0[0], acc0[1]);
                *(float2*)&red[base + (row + 8) * 16 + col    ] = make_float2(acc0[2], acc0[3]);
                *(float2*)&red[base +  row      * 16 + col + 8] = make_float2(acc1[0], acc1[1]);
                *(float2*)&red[base + (row + 8) * 16 + col + 8] = make_float2(acc1[2], acc1[3]);
            }
        }
        __syncthreads();

        // ---- K-split reduction (all 512 threads, one gate value each) ----
        {
            const int layer = tid >> 8, idx = tid & 255;
            const bool valid = layer ? (n >= 1) : (n < TT);
            if (valid) {
                const float* rp = &red[layer * 2048 + idx];
                float s = rp[0] + rp[256] + rp[512] + rp[768]
                        + rp[1024] + rp[1280] + rp[1536] + rp[1792];
                gv[tid] = s + bias[layer * 16 + (idx >> 4)];
            }
        }
        __syncthreads();

        // ---- activations + state update (LAYER==0 copy holds all act threads) ----
        if (LAYER == 0 && tid < 128) {
            const bool active = layerA ? (n >= 1) : (n < TT);
            if (active) {
                const int gb = layerA * 256 + uA * 16 + bA;
                float g0 = gv[gb];
                float g1 = gv[gb + 64];
                float g2 = gv[gb + 128];
                float g3 = gv[gb + 192];
                float iv = sigf(g0), fv = sigf(g1);
                float gg = tanh_fast(g2), ov = sigf(g3);
                c_reg = fv * c_reg + iv * gg;
                h_last = ov * tanh_fast(c_reg);

                float hp = __shfl_xor_sync(0xffffffffu, h_last, 16);
                if ((tid & 16) == 0) {
                    unsigned whi, wlo; split2(h_last, hp, whi, wlo);
                    int widx = j0 / 2 + (uA >> 1);
                    g_hHI[wr][layerA][bA][widx] = whi;
                    g_hLO[wr][layerA][bA][widx] = wlo;
                }
                if (layerA == 1) {
                    g_h2[((size_t)(n - 1) * BT + bA) * HID + j0 + uA] = h_last;
                }
            }
        }
        grid_barrier(n, tid);
    }

    if (LAYER == 0 && tid < 128) {
        const int j = j0 + uA;
        out[YSZ + (layerA * BT + bA) * HID + j] = h_last;
        out[YSZ + 2*BT*HID + (layerA * BT + bA) * HID + j] = c_reg;
    }
}

// ----------------- main persistent kernel -----------------------------------
__global__ void __launch_bounds__(NTH, 1) lstm_kernel(
    const float* __restrict__ w_ih0, const float* __restrict__ w_hh0,
    const float* __restrict__ b_ih0, const float* __restrict__ b_hh0,
    const float* __restrict__ w_ih1, const float* __restrict__ w_hh1,
    const float* __restrict__ b_ih1, const float* __restrict__ b_hh1,
    float* __restrict__ out)
{
    extern __shared__ unsigned smu[];
    float* red  = reinterpret_cast<float*>(&smu[ORED]);
    float* gv   = reinterpret_cast<float*>(&smu[OGV]);
    float* bias = reinterpret_cast<float*>(&smu[OBIAS]);
    const int tid = threadIdx.x;
    const int j0  = blockIdx.x * 4;

    // ---- one-time: split weights into bf16 hi/lo in shared ----
    // W0 rows r=g*4+u, words 0..319: k=[w_hh0(512) | w_ih0(32) | zero pad(96)]
    for (int i = tid; i < 16 * 320; i += NTH) {
        int r = i / 320, w = i - r * 320;
        int grow = (r >> 2) * HID + j0 + (r & 3);
        int k0 = 2 * w, k1 = k0 + 1;
        float f0 = (k0 < 512) ? w_hh0[grow*HID + k0]
                 : (k0 < 544) ? w_ih0[grow*ISZ + (k0 - 512)] : 0.0f;
        float f1 = (k1 < 512) ? w_hh0[grow*HID + k1]
                 : (k1 < 544) ? w_ih0[grow*ISZ + (k1 - 512)] : 0.0f;
        unsigned hi, lo; split2(f0, f1, hi, lo);
        smu[OW0HI + r * PW0W + w] = hi;
        smu[OW0LO + r * PW0W + w] = lo;
    }
    // W1 rows, words 0..511: cols [w_ih1 (vs h_a) | w_hh1 (vs h_b)]
    for (int i = tid; i < 16 * 512; i += NTH) {
        int r = i >> 9, w = i & 511;
        int grow = (r >> 2) * HID + j0 + (r & 3);
        int c0 = 2 * w, c1 = c0 + 1;
        float f0 = (c0 < 512) ? w_ih1[grow*HID + c0] : w_hh1[grow*HID + (c0 - 512)];
        float f1 = (c1 < 512) ? w_ih1[grow*HID + c1] : w_hh1[grow*HID + (c1 - 512)];
        unsigned hi, lo; split2(f0, f1, hi, lo);
        smu[OW1HI + r * PW1W + w] = hi;
        smu[OW1LO + r * PW1W + w] = lo;
    }
    if (tid < 32) {
        int l = tid >> 4, r = tid & 15;
        int grow = (r >> 2) * HID + j0 + (r & 3);
        bias[tid] = l ? (b_ih1[grow] + b_hh1[grow]) : (b_ih0[grow] + b_hh0[grow]);
    }
    // zero x pad words [272,288) of B rows, hi and lo
    for (int i = tid; i < 16 * 16; i += NTH) {
        int b = i >> 4, w = i & 15;
        smu[OHHI + b * PHW + 272 + w] = 0u;
        smu[OHLO + b * PHW + 272 + w] = 0u;
    }
    __syncthreads();

    const int wid = tid >> 5, lane = tid & 31;
    if (wid < 8)
        run_loop<0, 5>(smu, red, gv, bias, tid, wid, lane, wid * 5, j0, out);
    else
        run_loop<1, 8>(smu, red, gv, bias, tid, wid, lane, (wid - 8) * 8, j0, out);
}

// ----------------- y projection ---------------------------------------------
__global__ void __launch_bounds__(256) y_proj_kernel(
    const float* __restrict__ w_out, const float* __restrict__ b_out,
    float* __restrict__ out)
{
    extern __shared__ float sm[];
    float* sWo = sm;
    float* sH  = sm + 32 * PWO;
    const int t = blockIdx.x;
    const int tid = threadIdx.x;

    for (int i = tid; i < 32 * 128; i += 256) {
        int o = i >> 7, k = (i & 127) << 2;
        *(float4*)&sWo[o * PWO + k] = *(const float4*)&w_out[o * HID + k];
    }
    for (int i = tid; i < 16 * 128; i += 256) {
        int b = i >> 7, k = (i & 127) << 2;
        *(float4*)&sH[b * HID + k] = *(const float4*)&g_h2[((size_t)t * BT + b) * HID + k];
    }
    __syncthreads();

    const int b = tid >> 4, oc = tid & 15;
    float a0 = 0.0f, a1 = 0.0f;
    #pragma unroll 4
    for (int k = 0; k < HID; k += 4) {
        float4 hk = *(const float4*)&sH[b * HID + k];
        float4 w0 = *(const float4*)&sWo[oc * PWO + k];
        float4 w1 = *(const float4*)&sWo[(oc + 16) * PWO + k];
        a0 += hk.x*w0.x + hk.y*w0.y + hk.z*w0.z + hk.w*w0.w;
        a1 += hk.x*w1.x + hk.y*w1.y + hk.z*w1.z + hk.w*w1.w;
    }
    out[((size_t)b * TT + t) * ISZ + oc]      = a0 + b_out[oc];
    out[((size_t)b * TT + t) * ISZ + oc + 16] = a1 + b_out[oc + 16];
}

// ----------------------------------------------------------------------------
extern "C" void kernel_launch(void* const* d_in, const int* in_sizes, int n_in,
                              void* d_out, int out_size)
{
    const float* x     = (const float*)d_in[0];
    const float* w_ih0 = (const float*)d_in[1];
    const float* w_hh0 = (const float*)d_in[2];
    const float* b_ih0 = (const float*)d_in[3];
    const float* b_hh0 = (const float*)d_in[4];
    const float* w_ih1 = (const float*)d_in[5];
    const float* w_hh1 = (const float*)d_in[6];
    const float* b_ih1 = (const float*)d_in[7];
    const float* b_hh1 = (const float*)d_in[8];
    const float* w_out = (const float*)d_in[9];
    const float* b_out = (const float*)d_in[10];
    float* out = (float*)d_out;

    cudaFuncSetAttribute(lstm_kernel, cudaFuncAttributeMaxDynamicSharedMemorySize, SMEM_MAIN);
    cudaFuncSetAttribute(y_proj_kernel, cudaFuncAttributeMaxDynamicSharedMemorySize, SMEM_Y);

    init_zero_kernel<<<64, 256>>>();
    x_split_kernel<<<(TT*BT*16 + 255)/256, 256>>>(x);
    lstm_kernel<<<NBLK, NTH, SMEM_MAIN>>>(w_ih0, w_hh0, b_ih0, b_hh0,
                                          w_ih1, w_hh1, b_ih1, b_hh1, out);
    y_proj_kernel<<<TT, 256, SMEM_Y>>>(w_out, b_out, out);
}

// round 9
// speedup vs baseline: 1.6980x; 1.0203x over previous
#include <cuda_runtime.h>
#include <cuda_bf16.h>

#define HID 512
#define BT  16
#define TT  2048
#define ISZ 32
#define NBLK 128
#define NTH  512
#define YSZ (BT*TT*ISZ)

// ---- shared memory word (u32) layout ---------------------------------------
#define OA0   0                 // L0 A: hi 16x256 | lo 16x256 (w_hh0), swizzled
#define OA1   8192              // L1 A: hi 16x512 | lo 16x512 (w_ih1|w_hh1)
#define OB    24576             // B: hi [L(2)][b(16)][256] | lo same (raw copy of g_hp)
#define ORED  40960             // 16 warps x 256 floats
#define OBIAS 45056             // 32 floats
#define SMEM_MAIN ((OBIAS + 32) * 4)

#define PWO 516
#define SMEM_Y ((32*PWO + 16*512)*4)

// ---- device scratch ---------------------------------------------------------
__device__ __align__(16) unsigned g_hp[2][16384];   // packed split-bf16 h (64KB/buf)
__device__ float g_gx0[(size_t)TT*NBLK*256];        // precomputed x@w_ih0^T
__device__ float g_h2[(size_t)TT*BT*HID];           // layer-1 outputs
__device__ unsigned g_bar_count, g_bar_gen;

// ---- helpers ----------------------------------------------------------------
__device__ __forceinline__ void split2(float f0, float f1, unsigned &hi, unsigned &lo) {
    unsigned h;
    asm("cvt.rn.bf16x2.f32 %0, %1, %2;" : "=r"(h) : "f"(f1), "f"(f0));
    float r0 = f0 - __uint_as_float(h << 16);
    float r1 = f1 - __uint_as_float(h & 0xFFFF0000u);
    unsigned l;
    asm("cvt.rn.bf16x2.f32 %0, %1, %2;" : "=r"(l) : "f"(r1), "f"(r0));
    hi = h; lo = l;
}

__device__ __forceinline__ void mma_bf16(float* c, const unsigned* a, const unsigned* b) {
    asm volatile(
        "mma.sync.aligned.m16n8k16.row.col.f32.bf16.bf16.f32 "
        "{%0,%1,%2,%3}, {%4,%5,%6,%7}, {%8,%9}, {%0,%1,%2,%3};"
        : "+f"(c[0]), "+f"(c[1]), "+f"(c[2]), "+f"(c[3])
        : "r"(a[0]), "r"(a[1]), "r"(a[2]), "r"(a[3]), "r"(b[0]), "r"(b[1]));
}

__device__ __forceinline__ void ldsm4(unsigned &r0, unsigned &r1, unsigned &r2, unsigned &r3,
                                      unsigned addr) {
    asm volatile("ldmatrix.sync.aligned.m8n8.x4.shared.b16 {%0,%1,%2,%3}, [%4];"
                 : "=r"(r0), "=r"(r1), "=r"(r2), "=r"(r3) : "r"(addr));
}

__device__ __forceinline__ float sigf(float v) {
    return __fdividef(1.0f, 1.0f + __expf(-v));
}
__device__ __forceinline__ float tanh_fast(float v) {
    return __fdividef(2.0f, 1.0f + __expf(-2.0f * v)) - 1.0f;
}

// THE 3x-PROVEN grid barrier (R2/R3/R4): atomic ticket + volatile release word.
__device__ __forceinline__ void grid_barrier() {
    __syncthreads();
    if (threadIdx.x == 0) {
        volatile unsigned* genp = &g_bar_gen;
        unsigned gen = *genp;
        __threadfence();
        unsigned ticket = atomicAdd(&g_bar_count, 1u);
        if (ticket == NBLK - 1) {
            g_bar_count = 0u;   // reset before release
            __threadfence();
            atomicAdd(&g_bar_gen, 1u);
        } else {
            while (*genp == gen) { }
        }
    }
    __syncthreads();
}

// ---- init -------------------------------------------------------------------
__global__ void init_zero_kernel() {
    int i = blockIdx.x * blockDim.x + threadIdx.x;
    if (i < 2 * 16384) (&g_hp[0][0])[i] = 0u;
    if (i == 0) { g_bar_count = 0u; g_bar_gen = 0u; }
}

// gx0[t][blk][g*4+u][b] = dot(x[b,t,:], w_ih0[g*512+blk*4+u, :])
__global__ void gx0_kernel(const float* __restrict__ x, const float* __restrict__ w_ih0) {
    __shared__ float sx[BT][ISZ];
    const int t = blockIdx.x;
    const int tid = threadIdx.x;
    for (int i = tid; i < BT * ISZ; i += 256) {
        int b = i >> 5, k = i & 31;
        sx[b][k] = x[((size_t)b * TT + t) * ISZ + k];
    }
    __syncthreads();
    const int grow = blockIdx.y * 256 + tid;   // 0..2047
    float4 w[8];
    #pragma unroll
    for (int i = 0; i < 8; i++)
        w[i] = *(const float4*)&w_ih0[grow * ISZ + i * 4];
    const int g = grow >> 9, ug = grow & 511;
    const int blk = ug >> 2, u = ug & 3;
    float* outp = &g_gx0[((size_t)t * NBLK + blk) * 256 + (g * 4 + u) * 16];
    #pragma unroll 4
    for (int b = 0; b < BT; b++) {
        float s = 0.0f;
        #pragma unroll
        for (int i = 0; i < 8; i++) {
            s += w[i].x * sx[b][i*4+0] + w[i].y * sx[b][i*4+1]
               + w[i].z * sx[b][i*4+2] + w[i].w * sx[b][i*4+3];
        }
        outp[b] = s;
    }
}

// ---- main persistent kernel (plain launch, no clusters) ---------------------
__global__ void __launch_bounds__(NTH, 1) lstm_kernel(
    const float* __restrict__ w_hh0,
    const float* __restrict__ b_ih0, const float* __restrict__ b_hh0,
    const float* __restrict__ w_ih1, const float* __restrict__ w_hh1,
    const float* __restrict__ b_ih1, const float* __restrict__ b_hh1,
    float* __restrict__ out)
{
    extern __shared__ unsigned smu[];
    float* red  = reinterpret_cast<float*>(&smu[ORED]);
    float* bias = reinterpret_cast<float*>(&smu[OBIAS]);
    const int tid = threadIdx.x;
    const int bid = blockIdx.x;
    const int j0  = bid * 4;
    const unsigned sbase = (unsigned)__cvta_generic_to_shared(smu);

    // ---- one-time: split-bf16 weights into smem, XOR-swizzled ----
    for (int i = tid; i < 16 * 256; i += NTH) {
        int r = i >> 8, w = i & 255;
        int grow = (r >> 2) * HID + j0 + (r & 3);
        float f0 = w_hh0[grow * HID + 2 * w];
        float f1 = w_hh0[grow * HID + 2 * w + 1];
        unsigned hi, lo; split2(f0, f1, hi, lo);
        int ws = w ^ ((r & 7) << 2);
        smu[OA0 + r * 256 + ws]        = hi;
        smu[OA0 + 4096 + r * 256 + ws] = lo;
    }
    for (int i = tid; i < 16 * 512; i += NTH) {
        int r = i >> 9, w = i & 511;
        int grow = (r >> 2) * HID + j0 + (r & 3);
        int c0 = 2 * w, c1 = c0 + 1;
        float f0 = (c0 < 512) ? w_ih1[grow*HID + c0] : w_hh1[grow*HID + (c0 - 512)];
        float f1 = (c1 < 512) ? w_ih1[grow*HID + c1] : w_hh1[grow*HID + (c1 - 512)];
        unsigned hi, lo; split2(f0, f1, hi, lo);
        int ws = w ^ ((r & 7) << 2);
        smu[OA1 + r * 512 + ws]        = hi;
        smu[OA1 + 8192 + r * 512 + ws] = lo;
    }
    if (tid < 32) {
        int l = tid >> 4, r = tid & 15;
        int grow = (r >> 2) * HID + j0 + (r & 3);
        bias[tid] = l ? (b_ih1[grow] + b_hh1[grow]) : (b_ih0[grow] + b_hh0[grow]);
    }
    __syncthreads();

    // ---- roles ----
    const int wid = tid >> 5, lane = tid & 31;
    const int mm = lane >> 3, rr = lane & 7;
    const int ar = rr + ((mm & 1) << 3);          // A ldmatrix row
    const unsigned aoff = (unsigned)((mm >> 1) << 2);
    const int bb = ((mm >> 1) << 3) + rr;         // B ldmatrix row (batch)
    const unsigned boff = (unsigned)((mm & 1) << 2);
    const unsigned xm = (unsigned)(rr << 2);      // swizzle xor
    const int layerA = tid >> 6, uA = (tid >> 4) & 3, bA = tid & 15;
    float c_reg = 0.0f, h_last = 0.0f;

    for (int n = 0; n <= TT; n++) {
        const int wr = n & 1, rd = wr ^ 1;

        // ---- prefetch gx0 (L0 act threads) ----
        float gx[4] = {0, 0, 0, 0};
        if (tid < 64 && n < TT) {
            const float* gp = &g_gx0[((size_t)n * NBLK + bid) * 256 + uA * 16 + bA];
            #pragma unroll
            for (int g = 0; g < 4; g++) gx[g] = __ldg(gp + g * 64);
        }

        // ---- stage packed h (raw linear copy; layout already swizzled) ----
        {
            const uint4* src = (const uint4*)&g_hp[rd][0];
            #pragma unroll
            for (int it = 0; it < 8; it++) {
                int i = tid + it * NTH;            // 0..4095
                *(uint4*)&smu[OB + i * 4] = __ldcg(&src[i]);
            }
        }
        __syncthreads();

        // ---- tensor-core GEMMs (split-bf16, A+B via ldmatrix) ----
        if (wid < 8) {
            if (n < TT) {   // layer 0: K=512, K-split 8, 4 k-tiles each
                float acc0[4] = {0,0,0,0}, acc1[4] = {0,0,0,0};
                const unsigned w0 = (unsigned)(wid * 32);
                #pragma unroll
                for (int i = 0; i < 4; i++) {
                    const unsigned w = w0 + i * 8;
                    unsigned aw = sbase + (OA0 + ar * 256 + ((w + aoff) ^ xm)) * 4u;
                    unsigned bw = sbase + (OB  + bb * 256 + ((w + boff) ^ xm)) * 4u;
                    unsigned ah[4], al[4], b0,b1,b2,b3, l0,l1,l2,l3;
                    ldsm4(ah[0], ah[1], ah[2], ah[3], aw);
                    ldsm4(al[0], al[1], al[2], al[3], aw + 4096 * 4u);
                    ldsm4(b0, b1, b2, b3, bw);
                    ldsm4(l0, l1, l2, l3, bw + 8192 * 4u);
                    unsigned bh0[2] = {b0, b1}, bh1[2] = {b2, b3};
                    unsigned bl0[2] = {l0, l1}, bl1[2] = {l2, l3};
                    mma_bf16(acc0, ah, bh0);
                    mma_bf16(acc0, ah, bl0);
                    mma_bf16(acc0, al, bh0);
                    mma_bf16(acc1, ah, bh1);
                    mma_bf16(acc1, ah, bl1);
                    mma_bf16(acc1, al, bh1);
                }
                const int base = wid * 256, row = lane >> 2, col = (lane & 3) * 2;
                *(float2*)&red[base +  row      * 16 + col    ] = make_float2(acc0[0], acc0[1]);
                *(float2*)&red[base + (row + 8) * 16 + col    ] = make_float2(acc0[2], acc0[3]);
                *(float2*)&red[base +  row      * 16 + col + 8] = make_float2(acc1[0], acc1[1]);
                *(float2*)&red[base + (row + 8) * 16 + col + 8] = make_float2(acc1[2], acc1[3]);
            }
        } else {
            if (n >= 1) {   // layer 1: K=1024, K-split 8, 8 k-tiles each
                float acc0[4] = {0,0,0,0}, acc1[4] = {0,0,0,0};
                const unsigned wA0 = (unsigned)((wid - 8) * 64);
                const unsigned Lb  = (wid >= 12) ? 4096u : 0u;
                const unsigned wB0 = (wid >= 12) ? wA0 - 256u : wA0;
                #pragma unroll
                for (int i = 0; i < 8; i++) {
                    const unsigned wA = wA0 + i * 8, wB = wB0 + i * 8;
                    unsigned aw = sbase + (OA1 + ar * 512 + ((wA + aoff) ^ xm)) * 4u;
                    unsigned bw = sbase + (OB + Lb + bb * 256 + ((wB + boff) ^ xm)) * 4u;
                    unsigned ah[4], al[4], b0,b1,b2,b3, l0,l1,l2,l3;
                    ldsm4(ah[0], ah[1], ah[2], ah[3], aw);
                    ldsm4(al[0], al[1], al[2], al[3], aw + 8192 * 4u);
                    ldsm4(b0, b1, b2, b3, bw);
                    ldsm4(l0, l1, l2, l3, bw + 8192 * 4u);
                    unsigned bh0[2] = {b0, b1}, bh1[2] = {b2, b3};
                    unsigned bl0[2] = {l0, l1}, bl1[2] = {l2, l3};
                    mma_bf16(acc0, ah, bh0);
                    mma_bf16(acc0, ah, bl0);
                    mma_bf16(acc0, al, bh0);
                    mma_bf16(acc1, ah, bh1);
                    mma_bf16(acc1, ah, bl1);
                    mma_bf16(acc1, al, bh1);
                }
                const int base = wid * 256, row = lane >> 2, col = (lane & 3) * 2;
                *(float2*)&red[base +  row      * 16 + col    ] = make_float2(acc0[0], acc0[1]);
                *(float2*)&red[base + (row + 8) * 16 + col    ] = make_float2(acc0[2], acc0[3]);
                *(float2*)&red[base +  row      * 16 + col + 8] = make_float2(acc1[0], acc1[1]);
                *(float2*)&red[base + (row + 8) * 16 + col + 8] = make_float2(acc1[2], acc1[3]);
            }
        }
        __syncthreads();

        // ---- merged reduce + activations + state update + publish ----
        if (tid < 128) {
            const bool active = layerA ? (n >= 1) : (n < TT);
            if (active) {
                float g4[4];
                const int rb = layerA * 2048;
                #pragma unroll
                for (int g = 0; g < 4; g++) {
                    const int row = g * 4 + uA;
                    const float* rp = &red[rb + row * 16 + bA];
                    float s = rp[0] + rp[256] + rp[512] + rp[768]
                            + rp[1024] + rp[1280] + rp[1536] + rp[1792];
                    g4[g] = s + bias[layerA * 16 + row] + gx[g];
                }
                float iv = sigf(g4[0]), fv = sigf(g4[1]);
                float gg = tanh_fast(g4[2]), ov = sigf(g4[3]);
                c_reg = fv * c_reg + iv * gg;
                h_last = ov * tanh_fast(c_reg);

                float hp = __shfl_xor_sync(0xffffffffu, h_last, 16);
                if ((tid & 16) == 0) {
                    unsigned whi, wlo; split2(h_last, hp, whi, wlo);
                    const int w  = bid * 2 + (uA >> 1);
                    const int ws = w ^ ((bA & 7) << 2);
                    g_hp[wr][layerA * 4096 + bA * 256 + ws]        = whi;
                    g_hp[wr][8192 + layerA * 4096 + bA * 256 + ws] = wlo;
                }
                if (layerA == 1)
                    g_h2[((size_t)(n - 1) * BT + bA) * HID + j0 + uA] = h_last;
            }
        }
        __threadfence();
        grid_barrier();
    }

    // ---- final h_n, c_n ----
    if (tid < 128) {
        const int j = j0 + uA;
        out[YSZ + (layerA * BT + bA) * HID + j] = h_last;
        out[YSZ + 2*BT*HID + (layerA * BT + bA) * HID + j] = c_reg;
    }
}

// ---- y projection -----------------------------------------------------------
__global__ void __launch_bounds__(256) y_proj_kernel(
    const float* __restrict__ w_out, const float* __restrict__ b_out,
    float* __restrict__ out)
{
    extern __shared__ float sm[];
    float* sWo = sm;
    float* sH  = sm + 32 * PWO;
    const int t = blockIdx.x;
    const int tid = threadIdx.x;

    for (int i = tid; i < 32 * 128; i += 256) {
        int o = i >> 7, k = (i & 127) << 2;
        *(float4*)&sWo[o * PWO + k] = *(const float4*)&w_out[o * HID + k];
    }
    for (int i = tid; i < 16 * 128; i += 256) {
        int b = i >> 7, k = (i & 127) << 2;
        *(float4*)&sH[b * HID + k] = *(const float4*)&g_h2[((size_t)t * BT + b) * HID + k];
    }
    __syncthreads();

    const int b = tid >> 4, oc = tid & 15;
    float a0 = 0.0f, a1 = 0.0f;
    #pragma unroll 4
    for (int k = 0; k < HID; k += 4) {
        float4 hk = *(const float4*)&sH[b * HID + k];
        float4 w0 = *(const float4*)&sWo[oc * PWO + k];
        float4 w1 = *(const float4*)&sWo[(oc + 16) * PWO + k];
        a0 += hk.x*w0.x + hk.y*w0.y + hk.z*w0.z + hk.w*w0.w;
        a1 += hk.x*w1.x + hk.y*w1.y + hk.z*w1.z + hk.w*w1.w;
    }
    out[((size_t)b * TT + t) * ISZ + oc]      = a0 + b_out[oc];
    out[((size_t)b * TT + t) * ISZ + oc + 16] = a1 + b_out[oc + 16];
}

// ----------------------------------------------------------------------------
extern "C" void kernel_launch(void* const* d_in, const int* in_sizes, int n_in,
                              void* d_out, int out_size)
{
    const float* x     = (const float*)d_in[0];
    const float* w_ih0 = (const float*)d_in[1];
    const float* w_hh0 = (const float*)d_in[2];
    const float* b_ih0 = (const float*)d_in[3];
    const float* b_hh0 = (const float*)d_in[4];
    const float* w_ih1 = (const float*)d_in[5];
    const float* w_hh1 = (const float*)d_in[6];
    const float* b_ih1 = (const float*)d_in[7];
    const float* b_hh1 = (const float*)d_in[8];
    const float* w_out = (const float*)d_in[9];
    const float* b_out = (const float*)d_in[10];
    float* out = (float*)d_out;

    cudaFuncSetAttribute(lstm_kernel, cudaFuncAttributeMaxDynamicSharedMemorySize, SMEM_MAIN);
    cudaFuncSetAttribute(y_proj_kernel, cudaFuncAttributeMaxDynamicSharedMemorySize, SMEM_Y);

    init_zero_kernel<<<128, 256>>>();
    {
        dim3 g(TT, 8, 1);
        gx0_kernel<<<g, 256>>>(x, w_ih0);
    }
    lstm_kernel<<<NBLK, NTH, SMEM_MAIN>>>(w_hh0, b_ih0, b_hh0,
                                          w_ih1, w_hh1, b_ih1, b_hh1, out);
    y_proj_kernel<<<TT, 256, SMEM_Y>>>(w_out, b_out, out);
}